// round 11
// baseline (speedup 1.0000x reference)
#include <cuda_runtime.h>
#include <cstdint>
#include <cstddef>

// ---------------- device scratch (module globals: allocation-free) ----------------
#define NODES_MAX 4096
#define SMAX 64
__device__ int g_order[NODES_MAX];
__device__ int g_segStart[SMAX];
__device__ int g_segCount[SMAX];

// ---------------- grouping kernel: counting sort of nodes by species ----------------
__global__ void group_kernel(const int* __restrict__ index, int N) {
    __shared__ int cnt[SMAX];
    __shared__ int cur[SMAX];
    int tid = threadIdx.x;
    if (tid < SMAX) cnt[tid] = 0;
    __syncthreads();
    for (int i = tid; i < N; i += blockDim.x)
        atomicAdd(&cnt[index[i] & (SMAX - 1)], 1);
    __syncthreads();
    if (tid == 0) {
        int run = 0;
        for (int s = 0; s < SMAX; s++) {
            g_segStart[s] = run;
            g_segCount[s] = cnt[s];
            cur[s] = run;
            run += cnt[s];
        }
    }
    __syncthreads();
    for (int i = tid; i < N; i += blockDim.x) {
        int s = index[i] & (SMAX - 1);
        int p = atomicAdd(&cur[s], 1);
        if (p < NODES_MAX) g_order[p] = i;
    }
}

// ---------------- f32x2 helpers ----------------
typedef unsigned long long ull;
static __device__ __forceinline__ ull pk2(float v) {        // (v, v)
    ull r;
    asm("mov.b64 %0, {%1, %1};" : "=l"(r) : "r"(__float_as_uint(v)));
    return r;
}
static __device__ __forceinline__ void fma2(ull& d, ull a, ull b) {
    asm("fma.rn.f32x2 %0, %1, %2, %0;" : "+l"(d) : "l"(a), "l"(b));
}
static __device__ __forceinline__ void unpk2(ull v, float& lo, float& hi) {
    unsigned int a, b;
    asm("mov.b64 {%0, %1}, %2;" : "=r"(a), "=r"(b) : "l"(v));
    lo = __uint_as_float(a);
    hi = __uint_as_float(b);
}
static __device__ __forceinline__ float lo2(ull v) {
    unsigned int a, b;
    asm("mov.b64 {%0, %1}, %2;" : "=r"(a), "=r"(b) : "l"(v));
    return __uint_as_float(a);
}
static __device__ __forceinline__ float hi2(ull v) {
    unsigned int a, b;
    asm("mov.b64 {%0, %1}, %2;" : "=r"(a), "=r"(b) : "l"(v));
    return __uint_as_float(b);
}

// ---------------- layout ----------------
// Per channel c the output row base o=(n*128+c)*729 satisfies o mod 4 == c mod 4.
// Phase h(c) = (-c) mod 4: quads cover elements [h, h+4*Kq), head/tail scalar.
// uw smem stores element e of channel c at j*JSTR + (e - h) (head wrapped to end),
// so quad LDS.128 at j*JSTR + 4*q is 16B-aligned.
#define CT 8
#define JSTR 732
#define CHSTR (9 * JSTR)               // 6588
#define UW_F (CT * CHSTR)              // 52704
#define WS_OFF UW_F
#define NP 32                          // nodes per pass
#define NPP 34                         // xs row stride (floats), even for LDS.64
#define XS_OFF (WS_OFF + 240)
#define XS_F (72 * NPP)                // 2448
#define OB_OFF (XS_OFF + XS_F)
#define SMEM_F (OB_OFF + NP)
#define SMEM_BYTES (SMEM_F * 4)        // 221,824 B

// ---------------- build helper ----------------
template<int MUL, int IRR, int KOFF, int IBASE>
static __device__ __forceinline__ void build_chunk(const float* __restrict__ up,
                                                   const float* __restrict__ ws,
                                                   float* __restrict__ uw, int tid) {
    for (int idx = tid; idx < 729 * IRR; idx += 512) {
        int ab  = idx / (9 * IRR);
        int rem = idx - ab * 9 * IRR;
        int j   = rem / IRR;
        int il  = rem - j * IRR;
        const float* ub = up + ((ab * 9 + j) * MUL) * IRR + il;
        float uv[MUL];
        #pragma unroll
        for (int k = 0; k < MUL; k++) uv[k] = __ldg(ub + k * IRR);
        float acc[8];
        #pragma unroll
        for (int c = 0; c < 8; c++) acc[c] = 0.f;
        #pragma unroll
        for (int k = 0; k < MUL; k++) {
            const float* wr = ws + (KOFF + k) * 8;
            #pragma unroll
            for (int c = 0; c < 8; c++) acc[c] += uv[k] * wr[c];
        }
        int e = ab * 9 + IBASE + il;
        #pragma unroll
        for (int c = 0; c < 8; c++) {
            const int hc = (4 - (c & 3)) & 3;
            int pos = (e >= hc) ? (e - hc) : (729 - hc + e);
            uw[c * CHSTR + j * JSTR + pos] = acc[c];
        }
    }
}

// ---------------- main kernel ----------------
// grid = (C/8, S), 512 threads = 16 warps: warp -> channel (wid>>1), half (wid&1).
// Register-blocked GEMM: per tile, uw quad dup-packed into 36 ull regs (once);
// node-pairs streamed from smem x-stage (9 broadcast LDS.64 each); 36 fma2;
// 2 STG.128 streaming stores per pair.
__global__ __launch_bounds__(512, 1)
void mace_kernel(const float* __restrict__ nf,
                 const float* __restrict__ u0, const float* __restrict__ u1,
                 const float* __restrict__ u2,
                 const float* __restrict__ w0, const float* __restrict__ w1,
                 const float* __restrict__ w2,
                 float* __restrict__ out, int C) {
    extern __shared__ float sm[];
    float* uw = sm;
    float* ws = sm + WS_OFF;
    float* xs = sm + XS_OFF;                  // [72 rows][NPP]
    unsigned* ob = (unsigned*)(sm + OB_OFF);  // [NP] node row bases

    const int s = blockIdx.y;
    const int m = g_segCount[s];
    if (m == 0) return;             // CTA-uniform, before any barrier
    const int c0 = blockIdx.x * CT;
    const int segBase = g_segStart[s];
    const int tid = threadIdx.x;

    // ---- stage scaled species weights: ws[kglobal][c] ----
    if (tid < 240) {
        int kg = tid >> 3, c = tid & 7;
        const float* wp; int k; float scale; int mul;
        if (kg < 7)       { wp = w0; k = kg;      scale = 0.61478815f; mul = 7;  }
        else if (kg < 18) { wp = w1; k = kg - 7;  scale = 0.54910049f; mul = 11; }
        else              { wp = w2; k = kg - 18; scale = 0.53728497f; mul = 12; }
        ws[tid] = wp[((size_t)s * mul + k) * C + (c0 + c)] * scale;
    }
    __syncthreads();

    // ---- build uw (shifted layout) ----
    build_chunk<7, 1, 0, 0>(u0, ws, uw, tid);
    build_chunk<11, 3, 7, 1>(u1, ws, uw, tid);
    build_chunk<12, 5, 18, 4>(u2, ws, uw, tid);

    // ---- warp setup ----
    const int lane = tid & 31;
    const int wid  = tid >> 5;            // 0..15
    const int ch   = wid >> 1;            // channel in tile
    const int q    = wid & 1;             // pair-parity
    const int crow = c0 + ch;
    const float* uwC = uw + ch * CHSTR;
    const float* xsC = xs + ch * 9 * NPP;
    const unsigned crowOff = (unsigned)crow * 729u;
    const int h  = (4 - (crow & 3)) & 3;  // warp-uniform phase
    const int Kq = (729 - h) >> 2;        // full quads
    const int nL = 729 - 4 * Kq;          // leftover scalars (<=5)

    // ---- node passes ----
    for (int pb = 0; pb < m; pb += NP) {
        __syncthreads();                  // uw build done / xs reuse safe
        const int mp = (m - pb < NP) ? (m - pb) : NP;

        // stage xs (x values, channel-tile rows) + ob (node row bases)
        for (int idx = tid; idx < mp * 72; idx += 512) {
            int nd = idx / 72, r = idx - nd * 72;
            int nid = g_order[segBase + pb + nd];
            xs[r * NPP + nd] = nf[(size_t)nid * C * 9 + c0 * 9 + r];
            if (r == 0) ob[nd] = (unsigned)nid * (unsigned)(C * 729);
        }
        __syncthreads();

        const int npairs = (mp + 1) >> 1;

        // tiles of 32 quads
        #pragma unroll 1
        for (int t = 0; t < 6; t++) {
            int qi = t * 32 + lane;
            bool act = qi < Kq;
            int qc = act ? qi : 0;
            int soff = 4 * qc;
            // load + dup-pack uw quad: ud[j][el] = (uw[e], uw[e])
            ull ud[9][4];
            #pragma unroll
            for (int j = 0; j < 9; j++) {
                ulonglong2 v = *reinterpret_cast<const ulonglong2*>(uwC + j * JSTR + soff);
                float e0, e1, e2, e3;
                unpk2(v.x, e0, e1);
                unpk2(v.y, e2, e3);
                ud[j][0] = pk2(e0); ud[j][1] = pk2(e1);
                ud[j][2] = pk2(e2); ud[j][3] = pk2(e3);
            }
            int E = h + 4 * qc;

            #pragma unroll 1
            for (int p = q; p < npairs; p += 2) {
                // node-pair x: xp[j] = (x[nA][j], x[nB][j]) via broadcast LDS.64
                ull xp[9];
                #pragma unroll
                for (int j = 0; j < 9; j++)
                    xp[j] = *reinterpret_cast<const ull*>(xsC + j * NPP + 2 * p);
                ull acc[4] = {0ull, 0ull, 0ull, 0ull};
                #pragma unroll
                for (int j = 0; j < 9; j++) {
                    fma2(acc[0], ud[j][0], xp[j]);
                    fma2(acc[1], ud[j][1], xp[j]);
                    fma2(acc[2], ud[j][2], xp[j]);
                    fma2(acc[3], ud[j][3], xp[j]);
                }
                unsigned oA = ob[2 * p] + crowOff;
                unsigned oB = ob[2 * p + 1] + crowOff;
                bool vA = (pb + 2 * p) < m;
                bool vB = (pb + 2 * p + 1) < m;
                if (act && vA) {
                    float4 f;
                    f.x = lo2(acc[0]); f.y = lo2(acc[1]);
                    f.z = lo2(acc[2]); f.w = lo2(acc[3]);
                    __stcs(reinterpret_cast<float4*>(out + oA + E), f);
                }
                if (act && vB) {
                    float4 f;
                    f.x = hi2(acc[0]); f.y = hi2(acc[1]);
                    f.z = hi2(acc[2]); f.w = hi2(acc[3]);
                    __stcs(reinterpret_cast<float4*>(out + oB + E), f);
                }
            }
        }

        // tail scalars: head [0,h) + tail [h+4Kq, 729), nL lanes
        if (nL > 0) {
            #pragma unroll 1
            for (int p = q; p < npairs; p += 2) {
                if (lane < nL) {
                    int e   = (lane < h) ? lane : (4 * Kq + lane);
                    int pos = (lane < h) ? (729 - h + lane) : (4 * Kq + lane - h);
                    float bA = 0.f, bB = 0.f;
                    #pragma unroll
                    for (int j = 0; j < 9; j++) {
                        float uvv = uwC[j * JSTR + pos];
                        bA += uvv * xsC[j * NPP + 2 * p];
                        bB += uvv * xsC[j * NPP + 2 * p + 1];
                    }
                    unsigned oA = ob[2 * p] + crowOff;
                    unsigned oB = ob[2 * p + 1] + crowOff;
                    if ((pb + 2 * p) < m)     __stcs(out + oA + e, bA);
                    if ((pb + 2 * p + 1) < m) __stcs(out + oB + e, bB);
                }
            }
        }
    }
}

// ---------------- launch ----------------
extern "C" void kernel_launch(void* const* d_in, const int* in_sizes, int n_in,
                              void* d_out, int out_size) {
    const float *nf = nullptr, *u0 = nullptr, *u1 = nullptr, *u2 = nullptr;
    const float *w0 = nullptr, *w1 = nullptr, *w2 = nullptr;
    const int* index = nullptr;
    int N = 0, nf_sz = 0, w0_sz = 0;
    for (int i = 0; i < n_in; i++) {
        int sz = in_sizes[i];
        switch (sz) {
            case 5103:    u0 = (const float*)d_in[i]; break;
            case 24057:   u1 = (const float*)d_in[i]; break;
            case 43740:   u2 = (const float*)d_in[i]; break;
            case 44800:   w0 = (const float*)d_in[i]; w0_sz = sz; break;
            case 70400:   w1 = (const float*)d_in[i]; break;
            case 76800:   w2 = (const float*)d_in[i]; break;
            case 2048:    index = (const int*)d_in[i]; N = sz; break;
            case 2359296: nf = (const float*)d_in[i]; nf_sz = sz; break;
            default: break;
        }
    }
    if (!nf || !index || !u0 || !u1 || !u2 || !w0 || !w1 || !w2) return;

    const int C = nf_sz / (N * 9);        // 128
    const int S = w0_sz / (7 * C);        // 50

    group_kernel<<<1, 256>>>(index, N);

    cudaFuncSetAttribute(mace_kernel,
                         cudaFuncAttributeMaxDynamicSharedMemorySize, SMEM_BYTES);
    dim3 grid(C / CT, S);
    mace_kernel<<<grid, 512, SMEM_BYTES>>>(nf, u0, u1, u2, w0, w1, w2,
                                           (float*)d_out, C);
}